// round 17
// baseline (speedup 1.0000x reference)
#include <cuda.h>
#include <cuda_runtime.h>
#include <cuda_fp16.h>

#define FIN 512
#define HID 16
#define CO  7
#define NMAX 200000

// Scratch (no allocations allowed -> __device__ globals)
__device__ float g_deg [NMAX];
__device__ float g_dinv[NMAX];
__device__ __align__(16) __half g_g1h[NMAX * HID];  // RAW h1 = x@W1, f16
__device__ float g_t1  [NMAX * HID];   // scatter-add accum, layer 1 (f32)
__device__ float g_g2  [NMAX * 8];     // (relu(out1)@W2) * dinv[row], padded to 8
__device__ float g_t2  [NMAX * 8];     // scatter-add accum, layer 2 (f32)

typedef unsigned long long ull;

// ---------- helpers ----------
__device__ __forceinline__ void red4(float* p, float4 v) {
    asm volatile("red.global.add.v4.f32 [%0], {%1,%2,%3,%4};"
                 :: "l"(p), "f"(v.x), "f"(v.y), "f"(v.z), "f"(v.w) : "memory");
}
__device__ __forceinline__ void red1(float* p, float v) {
    asm volatile("red.global.add.f32 [%0], %1;" :: "l"(p), "f"(v) : "memory");
}
__device__ __forceinline__ void mbar_init(unsigned a, int cnt) {
    asm volatile("mbarrier.init.shared.b64 [%0], %1;" :: "r"(a), "r"(cnt) : "memory");
}
__device__ __forceinline__ void mbar_expect(unsigned a, int tx) {
    asm volatile("mbarrier.arrive.expect_tx.shared.b64 _, [%0], %1;"
                 :: "r"(a), "r"(tx) : "memory");
}
__device__ __forceinline__ void mbar_wait(unsigned a, int ph) {
    asm volatile(
        "{\n\t.reg .pred P;\n\t"
        "W_%=:\n\t"
        "mbarrier.try_wait.parity.acquire.cta.shared::cta.b64 P, [%0], %1, 0x989680;\n\t"
        "@!P bra W_%=;\n\t}"
        :: "r"(a), "r"(ph) : "memory");
}
__device__ __forceinline__ void tma2d(unsigned dst, const CUtensorMap* m,
                                      int cx, int cy, unsigned mbar) {
    asm volatile("cp.async.bulk.tensor.2d.shared::cta.global.tile."
                 "mbarrier::complete_tx::bytes [%0], [%1, {%2, %3}], [%4];"
                 :: "r"(dst), "l"(m), "r"(cx), "r"(cy), "r"(mbar) : "memory");
}
__device__ __forceinline__ unsigned f2tf32(float f) {
    unsigned r;
    asm("cvt.rna.tf32.f32 %0, %1;" : "=r"(r) : "f"(f));
    return r;
}
// Ampere-class warp MMA: m16n8k8 tf32 (valid on sm_103; no tcgen05 features)
__device__ __forceinline__ void mma_tf32(float* d, const unsigned* a, const unsigned* b) {
    asm volatile(
        "mma.sync.aligned.m16n8k8.row.col.f32.tf32.tf32.f32 "
        "{%0,%1,%2,%3}, {%4,%5,%6,%7}, {%8,%9}, {%0,%1,%2,%3};"
        : "+f"(d[0]), "+f"(d[1]), "+f"(d[2]), "+f"(d[3])
        : "r"(a[0]), "r"(a[1]), "r"(a[2]), "r"(a[3]), "r"(b[0]), "r"(b[1]));
}

// ---------- kernels ----------
// deg was memset to 0; +1 accounts for the self-loop
__global__ void k_dinv(int n) {
    int i = blockIdx.x * blockDim.x + threadIdx.x;
    if (i < n) g_dinv[i] = rsqrtf(g_deg[i] + 1.0f);
}

// ---------------------------------------------------------------------------
// FUSED kernel: interleaved block roles on one launch (no streams needed).
//  - xform blocks: h1raw[row] = x[row] @ W1 (tf32 mma.sync), f16 output.
//    x via TMA SW128 tiles (16 KB, ring of 4 slots + mbarrier); W1 staged
//    to smem pre-rounded to tf32.  DRAM/tensor-bound.
//  - deg blocks (every 7th block, NDEG total, grid-stride): deg scatter-add.
//    L2/RED-bound -> overlaps with xform instead of serializing before it.
// ---------------------------------------------------------------------------
#define XB     256
#define XROWS  128
#define KT     32                    // k per TMA tile (128 B rows)
#define NT     (FIN / KT)            // 16 tiles
#define NSTG   4
#define NDEG   256                   // deg blocks interleaved into the grid
#define SLOTB  (XROWS * 128)         // 16384 B
#define OFF_SLOT 1024
#define OFF_W    (OFF_SLOT + NSTG * SLOTB)        // 66560
#define XSMEM    (OFF_W + FIN * 17 * 4)           // 101376 B

__global__ void __launch_bounds__(XB) k_fused(const __grid_constant__ CUtensorMap tmap,
                                              const float* __restrict__ W1,
                                              const int* __restrict__ dstIdx,
                                              int n, int E) {
    const int bid = blockIdx.x;
    const int q = bid / 7, r = bid % 7;

    // ---- deg role: every 7th block (r==3), grid-stride over edges ----
    if (r == 3 && q < NDEG) {
        const int stride = NDEG * XB;
        for (int e = q * XB + threadIdx.x; e < E; e += stride)
            red1(&g_deg[dstIdx[e]], 1.0f);
        return;
    }
    const int xbid = bid - ((bid >= 7 * NDEG) ? NDEG : (q + (r > 3)));

    // ---- xform role ----
    extern __shared__ float smem[];
    const int tid  = threadIdx.x;
    const int wid  = tid >> 5;
    const int lane = tid & 31;
    const int g    = lane >> 2;
    const int t4   = lane & 3;
    const int rowBase = xbid * XROWS;

    unsigned sbase = (unsigned)__cvta_generic_to_shared(smem);

    // stage W1 -> smem as tf32 bits, [k][17] layout
    unsigned* Wu = (unsigned*)((char*)smem + OFF_W);
    for (int i = tid; i < FIN * HID; i += XB) {
        int k = i >> 4, nn = i & 15;
        Wu[k * 17 + nn] = f2tf32(W1[i]);
    }

    if (tid == 0)
#pragma unroll
        for (int s = 0; s < NSTG; s++) mbar_init(sbase + 8 * s, 1);
    __syncthreads();

    if (tid == 0) {
#pragma unroll
        for (int s = 0; s < NSTG; s++) {
            mbar_expect(sbase + 8 * s, SLOTB);
            tma2d(sbase + OFF_SLOT + (unsigned)s * SLOTB, &tmap, s * KT, rowBase,
                  sbase + 8 * s);
        }
    }

    float acc[2][4] = {{0.f, 0.f, 0.f, 0.f}, {0.f, 0.f, 0.f, 0.f}};
    const int ra = wid * 16 + g;
    const char* slot0 = (const char*)smem + OFF_SLOT;

#pragma unroll 1
    for (int t = 0; t < NT; t++) {
        int s  = t & (NSTG - 1);
        int ph = (t >> 2) & 1;
        mbar_wait(sbase + 8 * s, ph);

        const char* tile = slot0 + s * SLOTB;
        int kt = t * KT;
#pragma unroll
        for (int kst = 0; kst < 4; kst++) {
            int c0 = kst * 8 + t4;
            unsigned ax0 = (unsigned)(ra * 128)       + (((unsigned)(c0 * 4)) ^ ((unsigned)(ra & 7) * 16u));
            unsigned ax1 = (unsigned)((ra + 8) * 128) + (((unsigned)(c0 * 4)) ^ ((unsigned)(ra & 7) * 16u));
            unsigned a[4];
            a[0] = f2tf32(*(const float*)(tile + ax0));
            a[1] = f2tf32(*(const float*)(tile + ax1));
            a[2] = f2tf32(*(const float*)(tile + (ax0 ^ 16u)));
            a[3] = f2tf32(*(const float*)(tile + (ax1 ^ 16u)));
            int kb = kt + kst * 8 + t4;
#pragma unroll
            for (int nt = 0; nt < 2; nt++) {
                unsigned b[2];
                b[0] = Wu[kb * 17 + nt * 8 + g];
                b[1] = Wu[(kb + 4) * 17 + nt * 8 + g];
                mma_tf32(acc[nt], a, b);
            }
        }

        __syncthreads();
        if (tid == 0 && t + NSTG < NT) {
            mbar_expect(sbase + 8 * s, SLOTB);
            tma2d(sbase + OFF_SLOT + (unsigned)s * SLOTB, &tmap,
                  (t + NSTG) * KT, rowBase, sbase + 8 * s);
        }
    }

    // epilogue: raw h1 -> f16 (dinv applied later at gather / in k_mid)
    int gra = rowBase + ra, grb = gra + 8;
    if (gra < n) {
#pragma unroll
        for (int nt = 0; nt < 2; nt++)
            *(__half2*)&g_g1h[(size_t)gra * HID + nt * 8 + 2 * t4] =
                __floats2half2_rn(acc[nt][0], acc[nt][1]);
    }
    if (grb < n) {
#pragma unroll
        for (int nt = 0; nt < 2; nt++)
            *(__half2*)&g_g1h[(size_t)grb * HID + nt * 8 + 2 * t4] =
                __floats2half2_rn(acc[nt][2], acc[nt][3]);
    }
}

// scatter-add f32(h1raw[src]) * dinv[src] into t1[dst] — 2 threads/edge,
// 16 B f16 gather each (half the L2 gather traffic of f32), f32 RED.
__global__ void k_agg1(const int* __restrict__ src, const int* __restrict__ dst, int E) {
    int i = blockIdx.x * blockDim.x + threadIdx.x;
    int e = i >> 1;
    if (e >= E) return;
    int j = i & 1;
    int s = src[e], d = dst[e];
    float ds = g_dinv[s];
    uint4 hv = *(const uint4*)&g_g1h[(size_t)s * HID + j * 8];   // 8 halves
    __half2* hp = (__half2*)&hv;
    float2 p0 = __half22float2(hp[0]);
    float2 p1 = __half22float2(hp[1]);
    float2 p2 = __half22float2(hp[2]);
    float2 p3 = __half22float2(hp[3]);
    float* td = &g_t1[(size_t)d * HID + j * 8];
    red4(td,     make_float4(p0.x * ds, p0.y * ds, p1.x * ds, p1.y * ds));
    red4(td + 4, make_float4(p2.x * ds, p2.y * ds, p3.x * ds, p3.y * ds));
}

// out1 = relu(d*t1 + d*d*h1raw + b1);  g2 = (out1 @ W2) * d
__global__ void k_mid(const float* __restrict__ W2, const float* __restrict__ b1, int n) {
    int i = blockIdx.x * blockDim.x + threadIdx.x;
    if (i >= n) return;
    float d = g_dinv[i];
    float dd = d * d;
    uint4 u0 = *(const uint4*)&g_g1h[(size_t)i * HID];
    uint4 u1 = *(const uint4*)&g_g1h[(size_t)i * HID + 8];
    float gv[16];
    {
        __half2* hp = (__half2*)&u0;
#pragma unroll
        for (int p = 0; p < 4; p++) {
            float2 f = __half22float2(hp[p]);
            gv[2 * p] = f.x; gv[2 * p + 1] = f.y;
        }
        hp = (__half2*)&u1;
#pragma unroll
        for (int p = 0; p < 4; p++) {
            float2 f = __half22float2(hp[p]);
            gv[8 + 2 * p] = f.x; gv[8 + 2 * p + 1] = f.y;
        }
    }
    float h[16];
#pragma unroll
    for (int qq = 0; qq < 4; qq++) {
        float4 tv = *(const float4*)&g_t1[(size_t)i * HID + 4 * qq];
        h[4 * qq + 0] = fmaxf(d * tv.x + dd * gv[4 * qq + 0] + __ldg(&b1[4 * qq + 0]), 0.0f);
        h[4 * qq + 1] = fmaxf(d * tv.y + dd * gv[4 * qq + 1] + __ldg(&b1[4 * qq + 1]), 0.0f);
        h[4 * qq + 2] = fmaxf(d * tv.z + dd * gv[4 * qq + 2] + __ldg(&b1[4 * qq + 2]), 0.0f);
        h[4 * qq + 3] = fmaxf(d * tv.w + dd * gv[4 * qq + 3] + __ldg(&b1[4 * qq + 3]), 0.0f);
    }
    float o[CO];
#pragma unroll
    for (int j = 0; j < CO; j++) o[j] = 0.0f;
#pragma unroll
    for (int k = 0; k < HID; k++)
#pragma unroll
        for (int j = 0; j < CO; j++)
            o[j] = fmaf(h[k], __ldg(&W2[k * CO + j]), o[j]);
    float out8[8];
#pragma unroll
    for (int j = 0; j < CO; j++) out8[j] = o[j] * d;
    out8[7] = 0.0f;
    float4* dst4 = (float4*)&g_g2[(size_t)i * 8];
    dst4[0] = *(float4*)&out8[0];
    dst4[1] = *(float4*)&out8[4];
}

// scatter-add g2[src] into t2[dst] — 2 threads per edge (16B each, f32).
__global__ void k_agg2(const int* __restrict__ src, const int* __restrict__ dst, int E) {
    int i = blockIdx.x * blockDim.x + threadIdx.x;
    int e = i >> 1;
    if (e >= E) return;
    int j = i & 1;
    int s = src[e], d = dst[e];
    float4 v = __ldg((const float4*)&g_g2[(size_t)s * 8] + j);
    red4((float*)((float4*)&g_t2[(size_t)d * 8] + j), v);
}

// out = dinv*(t2 + g2) + b2
__global__ void k_final(const float* __restrict__ b2, float* __restrict__ out, int n) {
    int i = blockIdx.x * blockDim.x + threadIdx.x;
    if (i >= n) return;
    float d = g_dinv[i];
#pragma unroll
    for (int j = 0; j < CO; j++)
        out[(size_t)i * CO + j] =
            d * (g_t2[(size_t)i * 8 + j] + g_g2[(size_t)i * 8 + j]) + __ldg(&b2[j]);
}

// ---------- host: tensor-map encode via runtime entry point (no -lcuda) ----
typedef CUresult (*tme_fn_t)(CUtensorMap*, CUtensorMapDataType, cuuint32_t, void*,
                             const cuuint64_t*, const cuuint64_t*, const cuuint32_t*,
                             const cuuint32_t*, CUtensorMapInterleave, CUtensorMapSwizzle,
                             CUtensorMapL2promotion, CUtensorMapFloatOOBfill);

static tme_fn_t get_encoder() {
    static tme_fn_t fn = nullptr;
    if (!fn) {
        void* p = nullptr;
        cudaDriverEntryPointQueryResult st;
#if CUDART_VERSION >= 12050
        cudaGetDriverEntryPointByVersion("cuTensorMapEncodeTiled", &p, 12000,
                                         cudaEnableDefault, &st);
#else
        cudaGetDriverEntryPoint("cuTensorMapEncodeTiled", &p, cudaEnableDefault, &st);
#endif
        fn = (tme_fn_t)p;
    }
    return fn;
}

// ---------- launch ----------
extern "C" void kernel_launch(void* const* d_in, const int* in_sizes, int n_in,
                              void* d_out, int out_size) {
    const float* x  = (const float*)d_in[0];
    const int*   ei = (const int*)  d_in[1];
    const float* W1 = (const float*)d_in[2];
    const float* b1 = (const float*)d_in[3];
    const float* W2 = (const float*)d_in[4];
    const float* b2 = (const float*)d_in[5];

    int n = in_sizes[0] / FIN;
    int E = in_sizes[1] / 2;
    const int* src = ei;
    const int* dst = ei + E;

    static int init_done = 0;
    static void *pDeg, *pT1, *pT2;
    if (!init_done) {
        cudaGetSymbolAddress(&pDeg, g_deg);
        cudaGetSymbolAddress(&pT1, g_t1);
        cudaGetSymbolAddress(&pT2, g_t2);
        cudaFuncSetAttribute(k_fused, cudaFuncAttributeMaxDynamicSharedMemorySize, XSMEM);
        init_done = 1;
    }

    // TMA descriptor for x: [FIN contiguous] x [n rows], box [KT,128], SW128
    CUtensorMap tmap;
    {
        cuuint64_t dims[2]    = {(cuuint64_t)FIN, (cuuint64_t)n};
        cuuint64_t strides[1] = {(cuuint64_t)FIN * 4};
        cuuint32_t box[2]     = {KT, XROWS};
        cuuint32_t es[2]      = {1, 1};
        get_encoder()(&tmap, CU_TENSOR_MAP_DATA_TYPE_FLOAT32, 2, (void*)x,
                      dims, strides, box, es,
                      CU_TENSOR_MAP_INTERLEAVE_NONE, CU_TENSOR_MAP_SWIZZLE_128B,
                      CU_TENSOR_MAP_L2_PROMOTION_L2_128B,
                      CU_TENSOR_MAP_FLOAT_OOB_FILL_NONE);
    }

    const int TB = 256;
    int gEdge2 = (2 * E + TB - 1) / TB;
    int gNode  = (n + TB - 1) / TB;
    int gXform = (n + XROWS - 1) / XROWS;
    int gFused = gXform + NDEG;

    // zero-init via DMA (graph-capturable memset nodes)
    cudaMemsetAsync(pDeg, 0, (size_t)n * 4, 0);
    cudaMemsetAsync(pT1,  0, (size_t)n * HID * 4, 0);
    cudaMemsetAsync(pT2,  0, (size_t)n * 8 * 4, 0);

    k_fused<<<gFused, XB, XSMEM>>>(tmap, W1, dst, n, E);   // xform + deg overlapped
    k_dinv <<<gNode,  TB>>>(n);
    k_agg1 <<<gEdge2, TB>>>(src, dst, E);
    k_mid  <<<gNode,  TB>>>(W2, b1, n);
    k_agg2 <<<gEdge2, TB>>>(src, dst, E);
    k_final<<<gNode,  TB>>>(b2, (float*)d_out, n);
}